// round 4
// baseline (speedup 1.0000x reference)
#include <cuda_runtime.h>
#include <cuda_bf16.h>

#define N 8192
#define MARGIN 0.2f
#define INV_LAMB 83.333336f   // 1 / 0.012

#define BLOCKS 256
#define ROWS_PER_BLOCK 32     // 256 * 32 = 8192
#define THREADS 512
#define CPT 16                // columns per thread: 512 * 16 = 8192
#define NU4 1024              // uint4 (8 bf16) per row
#define NF4 2048              // float4 per row

// ---- scratch (static __device__ globals; no allocations) ----
__device__ uint4  g_K4[(size_t)N * N / 8];     // K in bf16 (128 MB)
__device__ float  g_r[N];
__device__ float  g_c[N];
__device__ float  g_d[N];
__device__ float  g_partial[(size_t)BLOCKS * N];  // col partials (8 MB)
__device__ float  g_block_loss[BLOCKS];

__device__ __forceinline__ float warp_sum(float v) {
    v += __shfl_xor_sync(0xffffffffu, v, 16);
    v += __shfl_xor_sync(0xffffffffu, v, 8);
    v += __shfl_xor_sync(0xffffffffu, v, 4);
    v += __shfl_xor_sync(0xffffffffu, v, 2);
    v += __shfl_xor_sync(0xffffffffu, v, 1);
    return v;
}

__device__ __forceinline__ float2 unpack_bf2(unsigned u) {
    float2 f;
    f.x = __uint_as_float(u << 16);
    f.y = __uint_as_float(u & 0xffff0000u);
    return f;
}

__device__ __forceinline__ unsigned pack_bf2(float lo, float hi) {
    __nv_bfloat162 h = __floats2bfloat162_rn(lo, hi);
    return *reinterpret_cast<unsigned*>(&h);
}

__device__ __forceinline__ void unpack16(const uint4& a, const uint4& b, float* k) {
    float2 p;
    p = unpack_bf2(a.x); k[0] = p.x;  k[1] = p.y;
    p = unpack_bf2(a.y); k[2] = p.x;  k[3] = p.y;
    p = unpack_bf2(a.z); k[4] = p.x;  k[5] = p.y;
    p = unpack_bf2(a.w); k[6] = p.x;  k[7] = p.y;
    p = unpack_bf2(b.x); k[8] = p.x;  k[9] = p.y;
    p = unpack_bf2(b.y); k[10] = p.x; k[11] = p.y;
    p = unpack_bf2(b.z); k[12] = p.x; k[13] = p.y;
    p = unpack_bf2(b.w); k[14] = p.x; k[15] = p.y;
}

// Block reduce of one float per thread -> total (all threads get it).
// Uses alternating smem slot (parity) so only ONE __syncthreads per call.
__device__ __forceinline__ float block_sum_512(float s, float red[2][16],
                                               int parity, int wid, int lane) {
    s = warp_sum(s);
    if (lane == 0) red[parity][wid] = s;
    __syncthreads();
    float tot = 0.f;
    #pragma unroll
    for (int w = 0; w < 16; w++) tot += red[parity][w];
    return tot;
}

// ============================================================================
// pass1_fused: K = exp((s-1)/lamb) -> bf16 cache; row update with c == 1
// (r_i = 1/sum_j K_ij); col partials with new r.  One read of sims.
// ============================================================================
__global__ __launch_bounds__(THREADS, 1) void pass1_fused(const float* __restrict__ sims) {
    int t = threadIdx.x;
    int wid = t >> 5, lane = t & 31;
    int row0 = blockIdx.x * ROWS_PER_BLOCK;
    __shared__ float red[2][16];

    const float4* __restrict__ sbase = (const float4*)sims + (size_t)row0 * NF4 + t * 4;
    uint4* __restrict__ kbase = g_K4 + (size_t)row0 * NU4 + t * 2;

    float acc[CPT];
    #pragma unroll
    for (int i = 0; i < CPT; i++) acc[i] = 0.f;

    float4 buf[4][4];   // prefetch ring, distance 2
    #pragma unroll
    for (int q = 0; q < 4; q++) { buf[0][q] = sbase[q]; buf[1][q] = sbase[NF4 + q]; }

    #pragma unroll 4
    for (int r = 0; r < ROWS_PER_BLOCK; r++) {
        // prefetch row r+2 (clamped)
        int pf = (r + 2 < ROWS_PER_BLOCK) ? (r + 2) : (ROWS_PER_BLOCK - 1);
        {
            const float4* p = sbase + (size_t)pf * NF4;
            int slot = (r + 2) & 3;
            #pragma unroll
            for (int q = 0; q < 4; q++) buf[slot][q] = p[q];
        }
        int cs = r & 3;
        float k[CPT];
        #pragma unroll
        for (int q = 0; q < 4; q++) {
            float4 s = buf[cs][q];
            k[q * 4 + 0] = __expf((s.x - 1.0f) * INV_LAMB);
            k[q * 4 + 1] = __expf((s.y - 1.0f) * INV_LAMB);
            k[q * 4 + 2] = __expf((s.z - 1.0f) * INV_LAMB);
            k[q * 4 + 3] = __expf((s.w - 1.0f) * INV_LAMB);
        }
        // write bf16 K
        {
            uint4 o0, o1;
            o0.x = pack_bf2(k[0], k[1]);   o0.y = pack_bf2(k[2], k[3]);
            o0.z = pack_bf2(k[4], k[5]);   o0.w = pack_bf2(k[6], k[7]);
            o1.x = pack_bf2(k[8], k[9]);   o1.y = pack_bf2(k[10], k[11]);
            o1.z = pack_bf2(k[12], k[13]); o1.w = pack_bf2(k[14], k[15]);
            uint4* kp = kbase + (size_t)r * NU4;
            kp[0] = o0; kp[1] = o1;
        }
        // row sum (c == 1)
        float s0 = 0.f, s1 = 0.f, s2 = 0.f, s3 = 0.f;
        #pragma unroll
        for (int i = 0; i < CPT; i += 4) {
            s0 += k[i]; s1 += k[i + 1]; s2 += k[i + 2]; s3 += k[i + 3];
        }
        float tot = block_sum_512((s0 + s1) + (s2 + s3), red, r & 1, wid, lane);
        float ri = 1.0f / tot;
        if (t == 0) g_r[row0 + r] = ri;
        #pragma unroll
        for (int i = 0; i < CPT; i++) acc[i] += k[i] * ri;
    }

    float4* out = (float4*)(g_partial + (size_t)blockIdx.x * N) + t * 4;
    #pragma unroll
    for (int q = 0; q < 4; q++)
        out[q] = make_float4(acc[q * 4], acc[q * 4 + 1], acc[q * 4 + 2], acc[q * 4 + 3]);
}

// ============================================================================
// fused_pass: one full Sinkhorn iteration's heavy work in ONE read of K:
// r_i = 1/sum_j K_ij c_j, then col partials sum_i K_ij r_i (new r).
// ============================================================================
__global__ __launch_bounds__(THREADS, 1) void fused_pass(void) {
    int t = threadIdx.x;
    int wid = t >> 5, lane = t & 31;
    int row0 = blockIdx.x * ROWS_PER_BLOCK;
    __shared__ float red[2][16];

    const uint4* __restrict__ kbase = g_K4 + (size_t)row0 * NU4 + t * 2;

    // loop-invariant c for my columns
    float c[CPT];
    {
        const float4* cp = (const float4*)g_c + t * 4;
        #pragma unroll
        for (int q = 0; q < 4; q++) {
            float4 v = cp[q];
            c[q * 4] = v.x; c[q * 4 + 1] = v.y; c[q * 4 + 2] = v.z; c[q * 4 + 3] = v.w;
        }
    }
    float acc[CPT];
    #pragma unroll
    for (int i = 0; i < CPT; i++) acc[i] = 0.f;

    uint4 buf[4][2];   // prefetch ring, distance 2
    buf[0][0] = kbase[0];        buf[0][1] = kbase[1];
    buf[1][0] = kbase[NU4];      buf[1][1] = kbase[NU4 + 1];

    #pragma unroll 4
    for (int r = 0; r < ROWS_PER_BLOCK; r++) {
        int pf = (r + 2 < ROWS_PER_BLOCK) ? (r + 2) : (ROWS_PER_BLOCK - 1);
        {
            const uint4* p = kbase + (size_t)pf * NU4;
            int slot = (r + 2) & 3;
            buf[slot][0] = p[0]; buf[slot][1] = p[1];
        }
        int cs = r & 3;
        float k[CPT];
        unpack16(buf[cs][0], buf[cs][1], k);

        float s0 = 0.f, s1 = 0.f, s2 = 0.f, s3 = 0.f;
        #pragma unroll
        for (int i = 0; i < CPT; i += 4) {
            s0 += k[i] * c[i];
            s1 += k[i + 1] * c[i + 1];
            s2 += k[i + 2] * c[i + 2];
            s3 += k[i + 3] * c[i + 3];
        }
        float tot = block_sum_512((s0 + s1) + (s2 + s3), red, r & 1, wid, lane);
        float ri = 1.0f / tot;
        if (t == 0) g_r[row0 + r] = ri;
        #pragma unroll
        for (int i = 0; i < CPT; i++) acc[i] += k[i] * ri;
    }

    float4* out = (float4*)(g_partial + (size_t)blockIdx.x * N) + t * 4;
    #pragma unroll
    for (int q = 0; q < 4; q++)
        out[q] = make_float4(acc[q * 4], acc[q * 4 + 1], acc[q * 4 + 2], acc[q * 4 + 3]);
}

// c_j = 1 / sum_b partial[b][j]
__global__ void col_reduce_kernel(void) {
    int jv = blockIdx.x * 256 + threadIdx.x;   // float4 index 0..2047
    float4 acc = make_float4(0.f, 0.f, 0.f, 0.f);
    #pragma unroll 8
    for (int b = 0; b < BLOCKS; b++) {
        float4 p = ((const float4*)g_partial)[(size_t)b * (N / 4) + jv];
        acc.x += p.x; acc.y += p.y; acc.z += p.z; acc.w += p.w;
    }
    float4 o;
    o.x = 1.0f / acc.x; o.y = 1.0f / acc.y; o.z = 1.0f / acc.z; o.w = 1.0f / acc.w;
    ((float4*)g_c)[jv] = o;
}

__global__ void diag_kernel(void) {
    int j = blockIdx.x * blockDim.x + threadIdx.x;
    const __nv_bfloat16* K = (const __nv_bfloat16*)g_K4;
    g_d[j] = __bfloat162float(K[(size_t)j * N + j]) * g_r[j] * g_c[j];
}

// ============================================================================
// loss_fused: block owns 32-row stripe; thread owns 16 cols. c_j and d_j are
// loop-invariant registers; r_i / d_i come from a small smem table. No per-row
// synchronization; single block reduction at the end.
// ============================================================================
__global__ __launch_bounds__(THREADS, 1) void loss_fused(void) {
    int t = threadIdx.x;
    int wid = t >> 5, lane = t & 31;
    int row0 = blockIdx.x * ROWS_PER_BLOCK;
    __shared__ float rsm[ROWS_PER_BLOCK], dsm[ROWS_PER_BLOCK];
    __shared__ float red[16];

    if (t < ROWS_PER_BLOCK) {
        rsm[t] = g_r[row0 + t];
        dsm[t] = g_d[row0 + t];
    }

    const uint4* __restrict__ kbase = g_K4 + (size_t)row0 * NU4 + t * 2;
    float c[CPT], dj[CPT];
    {
        const float4* cp = (const float4*)g_c + t * 4;
        const float4* dp = (const float4*)g_d + t * 4;
        #pragma unroll
        for (int q = 0; q < 4; q++) {
            float4 v = cp[q];
            c[q * 4] = v.x; c[q * 4 + 1] = v.y; c[q * 4 + 2] = v.z; c[q * 4 + 3] = v.w;
            float4 w = dp[q];
            dj[q * 4] = w.x; dj[q * 4 + 1] = w.y; dj[q * 4 + 2] = w.z; dj[q * 4 + 3] = w.w;
        }
    }
    __syncthreads();

    uint4 buf[4][2];
    buf[0][0] = kbase[0];        buf[0][1] = kbase[1];
    buf[1][0] = kbase[NU4];      buf[1][1] = kbase[NU4 + 1];

    int col0 = t * CPT;
    float l0 = 0.f, l1 = 0.f, l2 = 0.f, l3 = 0.f;

    #pragma unroll 4
    for (int r = 0; r < ROWS_PER_BLOCK; r++) {
        int pf = (r + 2 < ROWS_PER_BLOCK) ? (r + 2) : (ROWS_PER_BLOCK - 1);
        {
            const uint4* p = kbase + (size_t)pf * NU4;
            int slot = (r + 2) & 3;
            buf[slot][0] = p[0]; buf[slot][1] = p[1];
        }
        int cs = r & 3;
        float k[CPT];
        unpack16(buf[cs][0], buf[cs][1], k);

        float ri = rsm[r];
        float di = dsm[r];
        int row = row0 + r;
        #pragma unroll
        for (int i = 0; i < CPT; i++) {
            float P = k[i] * ri * c[i];
            float h = fmaxf(P - dj[i] + MARGIN, 0.f) + fmaxf(P - di + MARGIN, 0.f);
            h = (col0 + i != row) ? h : 0.f;
            if ((i & 3) == 0) l0 += h;
            else if ((i & 3) == 1) l1 += h;
            else if ((i & 3) == 2) l2 += h;
            else l3 += h;
        }
    }

    float s = warp_sum((l0 + l1) + (l2 + l3));
    if (lane == 0) red[wid] = s;
    __syncthreads();
    if (wid == 0) {
        float v = (lane < 16) ? red[lane] : 0.f;
        v = warp_sum(v);
        if (lane == 0) g_block_loss[blockIdx.x] = v;
    }
}

__global__ void final_reduce_kernel(float* __restrict__ out) {
    __shared__ double sh[256];
    double acc = (threadIdx.x < BLOCKS) ? (double)g_block_loss[threadIdx.x] : 0.0;
    sh[threadIdx.x] = acc;
    __syncthreads();
    #pragma unroll
    for (int s = 128; s > 0; s >>= 1) {
        if (threadIdx.x < s) sh[threadIdx.x] += sh[threadIdx.x + s];
        __syncthreads();
    }
    if (threadIdx.x == 0) out[0] = (float)sh[0];
}

extern "C" void kernel_launch(void* const* d_in, const int* in_sizes, int n_in,
                              void* d_out, int out_size) {
    const float* sims = (const float*)d_in[0];
    float* out = (float*)d_out;

    // iteration 1: K materialization + row update (c==1) + col partials
    pass1_fused<<<BLOCKS, THREADS>>>(sims);
    col_reduce_kernel<<<8, 256>>>();

    // iterations 2..5
    for (int it = 1; it < 5; it++) {
        fused_pass<<<BLOCKS, THREADS>>>();
        col_reduce_kernel<<<8, 256>>>();
    }

    diag_kernel<<<32, 256>>>();
    loss_fused<<<BLOCKS, THREADS>>>();
    final_reduce_kernel<<<1, 256>>>(out);
}

// round 5
// speedup vs baseline: 1.3356x; 1.3356x over previous
#include <cuda_runtime.h>
#include <cuda_bf16.h>

#define N 8192
#define MARGIN 0.2f
#define INV_LAMB 83.333336f   // 1 / 0.012

#define BLOCKS 256
#define ROWS_PER_BLOCK 32     // 256 * 32 = 8192
#define THREADS 512
#define CPT 16                // columns per thread: 512 * 16 = 8192
#define NU4 1024              // uint4 (8 bf16) per row
#define NF4 2048              // float4 per row
#define RGROUPS 16            // 256 partial rows -> 16 groups of 16

// ---- scratch (static __device__ globals; no allocations) ----
__device__ uint4  g_K4[(size_t)N * N / 8];        // K in bf16 (128 MB)
__device__ float  g_r[N];
__device__ float  g_c[N];
__device__ float  g_d[N];
__device__ float  g_partial[(size_t)BLOCKS * N];  // col partials (8 MB)
__device__ float  g_partial2[(size_t)RGROUPS * N];// stage-2 partials (512 KB)
__device__ float  g_block_loss[BLOCKS];

__device__ __forceinline__ float warp_sum(float v) {
    v += __shfl_xor_sync(0xffffffffu, v, 16);
    v += __shfl_xor_sync(0xffffffffu, v, 8);
    v += __shfl_xor_sync(0xffffffffu, v, 4);
    v += __shfl_xor_sync(0xffffffffu, v, 2);
    v += __shfl_xor_sync(0xffffffffu, v, 1);
    return v;
}

__device__ __forceinline__ float2 unpack_bf2(unsigned u) {
    float2 f;
    f.x = __uint_as_float(u << 16);
    f.y = __uint_as_float(u & 0xffff0000u);
    return f;
}

__device__ __forceinline__ unsigned pack_bf2(float lo, float hi) {
    __nv_bfloat162 h = __floats2bfloat162_rn(lo, hi);
    return *reinterpret_cast<unsigned*>(&h);
}

__device__ __forceinline__ void unpack16(const uint4& a, const uint4& b, float* k) {
    float2 p;
    p = unpack_bf2(a.x); k[0] = p.x;  k[1] = p.y;
    p = unpack_bf2(a.y); k[2] = p.x;  k[3] = p.y;
    p = unpack_bf2(a.z); k[4] = p.x;  k[5] = p.y;
    p = unpack_bf2(a.w); k[6] = p.x;  k[7] = p.y;
    p = unpack_bf2(b.x); k[8] = p.x;  k[9] = p.y;
    p = unpack_bf2(b.y); k[10] = p.x; k[11] = p.y;
    p = unpack_bf2(b.z); k[12] = p.x; k[13] = p.y;
    p = unpack_bf2(b.w); k[14] = p.x; k[15] = p.y;
}

// Block reduce of one float per thread -> total (all threads get it).
// Alternating smem slot (parity) so only ONE __syncthreads per call.
__device__ __forceinline__ float block_sum_512(float s, float red[2][16],
                                               int parity, int wid, int lane) {
    s = warp_sum(s);
    if (lane == 0) red[parity][wid] = s;
    __syncthreads();
    float tot = 0.f;
    #pragma unroll
    for (int w = 0; w < 16; w++) tot += red[parity][w];
    return tot;
}

// ============================================================================
// pass1_fused: K = exp((s-1)/lamb) -> bf16 cache; row update with c == 1
// (r_i = 1/sum_j K_ij); col partials with new r.  One read of sims.
// ============================================================================
__global__ __launch_bounds__(THREADS, 1) void pass1_fused(const float* __restrict__ sims) {
    int t = threadIdx.x;
    int wid = t >> 5, lane = t & 31;
    int row0 = blockIdx.x * ROWS_PER_BLOCK;
    __shared__ float red[2][16];

    const float4* __restrict__ sbase = (const float4*)sims + (size_t)row0 * NF4 + t * 4;
    uint4* __restrict__ kbase = g_K4 + (size_t)row0 * NU4 + t * 2;

    float acc[CPT];
    #pragma unroll
    for (int i = 0; i < CPT; i++) acc[i] = 0.f;

    float4 buf[4][4];   // prefetch ring, distance 2
    #pragma unroll
    for (int q = 0; q < 4; q++) { buf[0][q] = sbase[q]; buf[1][q] = sbase[NF4 + q]; }

    #pragma unroll 4
    for (int r = 0; r < ROWS_PER_BLOCK; r++) {
        int pf = (r + 2 < ROWS_PER_BLOCK) ? (r + 2) : (ROWS_PER_BLOCK - 1);
        {
            const float4* p = sbase + (size_t)pf * NF4;
            int slot = (r + 2) & 3;
            #pragma unroll
            for (int q = 0; q < 4; q++) buf[slot][q] = p[q];
        }
        int cs = r & 3;
        float k[CPT];
        #pragma unroll
        for (int q = 0; q < 4; q++) {
            float4 s = buf[cs][q];
            k[q * 4 + 0] = __expf((s.x - 1.0f) * INV_LAMB);
            k[q * 4 + 1] = __expf((s.y - 1.0f) * INV_LAMB);
            k[q * 4 + 2] = __expf((s.z - 1.0f) * INV_LAMB);
            k[q * 4 + 3] = __expf((s.w - 1.0f) * INV_LAMB);
        }
        {
            uint4 o0, o1;
            o0.x = pack_bf2(k[0], k[1]);   o0.y = pack_bf2(k[2], k[3]);
            o0.z = pack_bf2(k[4], k[5]);   o0.w = pack_bf2(k[6], k[7]);
            o1.x = pack_bf2(k[8], k[9]);   o1.y = pack_bf2(k[10], k[11]);
            o1.z = pack_bf2(k[12], k[13]); o1.w = pack_bf2(k[14], k[15]);
            uint4* kp = kbase + (size_t)r * NU4;
            kp[0] = o0; kp[1] = o1;
        }
        float s0 = 0.f, s1 = 0.f, s2 = 0.f, s3 = 0.f;
        #pragma unroll
        for (int i = 0; i < CPT; i += 4) {
            s0 += k[i]; s1 += k[i + 1]; s2 += k[i + 2]; s3 += k[i + 3];
        }
        float tot = block_sum_512((s0 + s1) + (s2 + s3), red, r & 1, wid, lane);
        float ri = 1.0f / tot;
        if (t == 0) g_r[row0 + r] = ri;
        #pragma unroll
        for (int i = 0; i < CPT; i++) acc[i] += k[i] * ri;
    }

    float4* out = (float4*)(g_partial + (size_t)blockIdx.x * N) + t * 4;
    #pragma unroll
    for (int q = 0; q < 4; q++)
        out[q] = make_float4(acc[q * 4], acc[q * 4 + 1], acc[q * 4 + 2], acc[q * 4 + 3]);
}

// ============================================================================
// fused_pass: one Sinkhorn iteration's heavy work in ONE read of K:
// r_i = 1/sum_j K_ij c_j, then col partials sum_i K_ij r_i (new r).
// ============================================================================
__global__ __launch_bounds__(THREADS, 1) void fused_pass(void) {
    int t = threadIdx.x;
    int wid = t >> 5, lane = t & 31;
    int row0 = blockIdx.x * ROWS_PER_BLOCK;
    __shared__ float red[2][16];

    const uint4* __restrict__ kbase = g_K4 + (size_t)row0 * NU4 + t * 2;

    float c[CPT];
    {
        const float4* cp = (const float4*)g_c + t * 4;
        #pragma unroll
        for (int q = 0; q < 4; q++) {
            float4 v = cp[q];
            c[q * 4] = v.x; c[q * 4 + 1] = v.y; c[q * 4 + 2] = v.z; c[q * 4 + 3] = v.w;
        }
    }
    float acc[CPT];
    #pragma unroll
    for (int i = 0; i < CPT; i++) acc[i] = 0.f;

    uint4 buf[4][2];
    buf[0][0] = kbase[0];        buf[0][1] = kbase[1];
    buf[1][0] = kbase[NU4];      buf[1][1] = kbase[NU4 + 1];

    #pragma unroll 4
    for (int r = 0; r < ROWS_PER_BLOCK; r++) {
        int pf = (r + 2 < ROWS_PER_BLOCK) ? (r + 2) : (ROWS_PER_BLOCK - 1);
        {
            const uint4* p = kbase + (size_t)pf * NU4;
            int slot = (r + 2) & 3;
            buf[slot][0] = p[0]; buf[slot][1] = p[1];
        }
        int cs = r & 3;
        float k[CPT];
        unpack16(buf[cs][0], buf[cs][1], k);

        float s0 = 0.f, s1 = 0.f, s2 = 0.f, s3 = 0.f;
        #pragma unroll
        for (int i = 0; i < CPT; i += 4) {
            s0 += k[i] * c[i];
            s1 += k[i + 1] * c[i + 1];
            s2 += k[i + 2] * c[i + 2];
            s3 += k[i + 3] * c[i + 3];
        }
        float tot = block_sum_512((s0 + s1) + (s2 + s3), red, r & 1, wid, lane);
        float ri = 1.0f / tot;
        if (t == 0) g_r[row0 + r] = ri;
        #pragma unroll
        for (int i = 0; i < CPT; i++) acc[i] += k[i] * ri;
    }

    float4* out = (float4*)(g_partial + (size_t)blockIdx.x * N) + t * 4;
    #pragma unroll
    for (int q = 0; q < 4; q++)
        out[q] = make_float4(acc[q * 4], acc[q * 4 + 1], acc[q * 4 + 2], acc[q * 4 + 3]);
}

// ============================================================================
// Two-stage tree reduction of g_partial[256][N] -> g_c
// ============================================================================
// stage 1: grid (8, RGROUPS); block 256. Block (x,g) sums partial rows
// [g*16, g*16+16) for float4 cols [x*256, x*256+256) -> g_partial2[g][...]
__global__ void col_reduce1(void) {
    int jv = blockIdx.x * 256 + threadIdx.x;   // float4 col index 0..2047
    int g  = blockIdx.y;
    const float4* __restrict__ p4 = (const float4*)g_partial;
    float4 acc = make_float4(0.f, 0.f, 0.f, 0.f);
    #pragma unroll
    for (int b = 0; b < 16; b++) {
        float4 p = p4[(size_t)(g * 16 + b) * (N / 4) + jv];
        acc.x += p.x; acc.y += p.y; acc.z += p.z; acc.w += p.w;
    }
    ((float4*)g_partial2)[(size_t)g * (N / 4) + jv] = acc;
}

// stage 2: grid 8; block 256. Sum 16 rows of partial2, write c = 1/v.
__global__ void col_reduce2(void) {
    int jv = blockIdx.x * 256 + threadIdx.x;
    const float4* __restrict__ p4 = (const float4*)g_partial2;
    float4 acc = make_float4(0.f, 0.f, 0.f, 0.f);
    #pragma unroll
    for (int g = 0; g < RGROUPS; g++) {
        float4 p = p4[(size_t)g * (N / 4) + jv];
        acc.x += p.x; acc.y += p.y; acc.z += p.z; acc.w += p.w;
    }
    float4 o;
    o.x = 1.0f / acc.x; o.y = 1.0f / acc.y; o.z = 1.0f / acc.z; o.w = 1.0f / acc.w;
    ((float4*)g_c)[jv] = o;
}

__global__ void diag_kernel(void) {
    int j = blockIdx.x * blockDim.x + threadIdx.x;
    const __nv_bfloat16* K = (const __nv_bfloat16*)g_K4;
    g_d[j] = __bfloat162float(K[(size_t)j * N + j]) * g_r[j] * g_c[j];
}

// ============================================================================
// loss_fused: block owns 32-row stripe; thread owns 16 cols. c_j, d_j are
// loop-invariant registers; r_i / d_i from a small smem table. No per-row
// sync; single block reduction at the end.
// ============================================================================
__global__ __launch_bounds__(THREADS, 1) void loss_fused(void) {
    int t = threadIdx.x;
    int wid = t >> 5, lane = t & 31;
    int row0 = blockIdx.x * ROWS_PER_BLOCK;
    __shared__ float rsm[ROWS_PER_BLOCK], dsm[ROWS_PER_BLOCK];
    __shared__ float red[16];

    if (t < ROWS_PER_BLOCK) {
        rsm[t] = g_r[row0 + t];
        dsm[t] = g_d[row0 + t];
    }

    const uint4* __restrict__ kbase = g_K4 + (size_t)row0 * NU4 + t * 2;
    float c[CPT], dj[CPT];
    {
        const float4* cp = (const float4*)g_c + t * 4;
        const float4* dp = (const float4*)g_d + t * 4;
        #pragma unroll
        for (int q = 0; q < 4; q++) {
            float4 v = cp[q];
            c[q * 4] = v.x; c[q * 4 + 1] = v.y; c[q * 4 + 2] = v.z; c[q * 4 + 3] = v.w;
            float4 w = dp[q];
            dj[q * 4] = w.x; dj[q * 4 + 1] = w.y; dj[q * 4 + 2] = w.z; dj[q * 4 + 3] = w.w;
        }
    }
    __syncthreads();

    uint4 buf[4][2];
    buf[0][0] = kbase[0];        buf[0][1] = kbase[1];
    buf[1][0] = kbase[NU4];      buf[1][1] = kbase[NU4 + 1];

    int col0 = t * CPT;
    float l0 = 0.f, l1 = 0.f, l2 = 0.f, l3 = 0.f;

    #pragma unroll 4
    for (int r = 0; r < ROWS_PER_BLOCK; r++) {
        int pf = (r + 2 < ROWS_PER_BLOCK) ? (r + 2) : (ROWS_PER_BLOCK - 1);
        {
            const uint4* p = kbase + (size_t)pf * NU4;
            int slot = (r + 2) & 3;
            buf[slot][0] = p[0]; buf[slot][1] = p[1];
        }
        int cs = r & 3;
        float k[CPT];
        unpack16(buf[cs][0], buf[cs][1], k);

        float ri = rsm[r];
        float di = dsm[r];
        int row = row0 + r;
        #pragma unroll
        for (int i = 0; i < CPT; i++) {
            float P = k[i] * ri * c[i];
            float h = fmaxf(P - dj[i] + MARGIN, 0.f) + fmaxf(P - di + MARGIN, 0.f);
            h = (col0 + i != row) ? h : 0.f;
            if ((i & 3) == 0) l0 += h;
            else if ((i & 3) == 1) l1 += h;
            else if ((i & 3) == 2) l2 += h;
            else l3 += h;
        }
    }

    float s = warp_sum((l0 + l1) + (l2 + l3));
    if (lane == 0) red[wid] = s;
    __syncthreads();
    if (wid == 0) {
        float v = (lane < 16) ? red[lane] : 0.f;
        v = warp_sum(v);
        if (lane == 0) g_block_loss[blockIdx.x] = v;
    }
}

__global__ void final_reduce_kernel(float* __restrict__ out) {
    __shared__ double sh[256];
    double acc = (threadIdx.x < BLOCKS) ? (double)g_block_loss[threadIdx.x] : 0.0;
    sh[threadIdx.x] = acc;
    __syncthreads();
    #pragma unroll
    for (int s = 128; s > 0; s >>= 1) {
        if (threadIdx.x < s) sh[threadIdx.x] += sh[threadIdx.x + s];
        __syncthreads();
    }
    if (threadIdx.x == 0) out[0] = (float)sh[0];
}

extern "C" void kernel_launch(void* const* d_in, const int* in_sizes, int n_in,
                              void* d_out, int out_size) {
    const float* sims = (const float*)d_in[0];
    float* out = (float*)d_out;

    // iteration 1: K materialization + row update (c==1) + col partials
    pass1_fused<<<BLOCKS, THREADS>>>(sims);
    col_reduce1<<<dim3(8, RGROUPS), 256>>>();
    col_reduce2<<<8, 256>>>();

    // iterations 2..5
    for (int it = 1; it < 5; it++) {
        fused_pass<<<BLOCKS, THREADS>>>();
        col_reduce1<<<dim3(8, RGROUPS), 256>>>();
        col_reduce2<<<8, 256>>>();
    }

    diag_kernel<<<32, 256>>>();
    loss_fused<<<BLOCKS, THREADS>>>();
    final_reduce_kernel<<<1, 256>>>(out);
}